// round 17
// baseline (speedup 1.0000x reference)
#include <cuda_runtime.h>
#include <cuda_fp16.h>
#include <cstdint>

typedef uint32_t u32;

#define NT     256
#define LMN    68
#define NTOT   77
#define XSTRB  176        // xT row bytes: [d 128][n 80] fp16 padded
#define YSTR   176        // Y  row bytes: [o 128][m 80] fp16 padded

// state block (per CTA = one graph)
#define XT_OF  0          // xT tile (128 x 176B = 22528)
#define Y_OF   22528      // Y  tile (128 x 176B = 22528)
#define GSZ    45056
#define O_G    (GSZ)
#define O_BE   (GSZ+512)
#define O_SS   (GSZ+1024)
#define O_SW   (GSZ+1408)
#define SMEM_SZ (GSZ+1792)   // 46848 B -> 2 CTAs/SM

// static operand tables (single fp16):
//   g_wf: W^T A-frags  (mma A layout)  [L4][o-band8][k=d 8][lane32] uint4
//   g_bf: adj^T B-frags (mma B layout) [k=m band5][n-blk10][lane32] uint2
__device__ uint4 g_wf[4*8*8*32];
__device__ uint2 g_bf[5*10*32];

__constant__ int2 c_reg[9] = {
  {0,16},{17,21},{22,26},{27,30},{31,35},{36,41},{42,47},{48,59},{60,67}
};

__device__ __forceinline__ u32 h2pack(float a, float b){ // low16=fp16(a), high16=fp16(b)
  __half2 h = __floats2half2_rn(a, b);
  return *(u32*)&h;
}
__device__ __forceinline__ void ldm4(u32* r, u32 addr){
  asm volatile("ldmatrix.sync.aligned.m8n8.x4.shared.b16 {%0,%1,%2,%3}, [%4];"
    : "=r"(r[0]),"=r"(r[1]),"=r"(r[2]),"=r"(r[3]) : "r"(addr));
}
__device__ __forceinline__ void ldm4t(u32* r, u32 addr){
  asm volatile("ldmatrix.sync.aligned.m8n8.x4.trans.shared.b16 {%0,%1,%2,%3}, [%4];"
    : "=r"(r[0]),"=r"(r[1]),"=r"(r[2]),"=r"(r[3]) : "r"(addr));
}
__device__ __forceinline__ void ldm2t(u32* r, u32 addr){
  asm volatile("ldmatrix.sync.aligned.m8n8.x2.trans.shared.b16 {%0,%1}, [%2];"
    : "=r"(r[0]),"=r"(r[1]) : "r"(addr));
}
__device__ __forceinline__ void mma(float* c, const u32* a, u32 b0, u32 b1){
  asm volatile("mma.sync.aligned.m16n8k16.row.col.f32.f16.f16.f32 "
    "{%0,%1,%2,%3},{%4,%5,%6,%7},{%8,%9},{%0,%1,%2,%3};"
    : "+f"(c[0]),"+f"(c[1]),"+f"(c[2]),"+f"(c[3])
    : "r"(a[0]),"r"(a[1]),"r"(a[2]),"r"(a[3]), "r"(b0),"r"(b1));
}

// ---------------- format kernel: build static frag tables ----------------
__global__ void __launch_bounds__(256)
format_kernel(const float* __restrict__ adj,
              const float* __restrict__ W0, const float* __restrict__ W1,
              const float* __restrict__ W2, const float* __restrict__ W3)
{
  const int b = blockIdx.x;
  const float* Ws[4] = {W0,W1,W2,W3};
  if (b == 0){
    // adj^T B-frags: frag (kb: m-band of 16, j: n-block of 8)
    for (int idx = threadIdx.x; idx < 5*10*32; idx += 256){
      int lane = idx & 31, j = (idx >> 5) % 10, kb = idx / 320;
      int n  = j*8 + (lane>>2);
      int m0 = kb*16 + (lane&3)*2;
      float p0=0.f,q0=0.f,p1=0.f,q1=0.f;
      if (n < NTOT){
        if (m0   < NTOT) p0 = adj[n*NTOT + m0];
        if (m0+1 < NTOT) q0 = adj[n*NTOT + m0+1];
        if (m0+8 < NTOT) p1 = adj[n*NTOT + m0+8];
        if (m0+9 < NTOT) q1 = adj[n*NTOT + m0+9];
      }
      g_bf[(kb*10 + j)*32 + lane] = make_uint2(h2pack(p0,q0), h2pack(p1,q1));
    }
  } else {
    // W^T A-frags (row-major 16o x 16d), k = d
    const float* W = Ws[b-1];
    for (int idx = threadIdx.x; idx < 8*8*32; idx += 256){
      int lane = idx & 31, k = (idx >> 5) & 7, band = idx >> 8;
      u32 H[4];
      #pragma unroll
      for (int j = 0; j < 4; j++){
        int row = band*16 + (lane>>2) + (j&1)*8;   // o
        int cd  = k*16 + (lane&3)*2 + (j>>1)*8;    // d
        H[j] = h2pack(W[cd*128 + row], W[(cd+1)*128 + row]);
      }
      g_wf[(((b-1)*8 + band)*8 + k)*32 + lane] = make_uint4(H[0],H[1],H[2],H[3]);
    }
  }
}

// ---------------- main kernel: one graph per 256-thread CTA, 2 CTAs/SM ----------------
__global__ void __launch_bounds__(NT, 2)
net_kernel(const float* __restrict__ lm,
           const float* __restrict__ Wr, const float* __restrict__ br,
           const float* __restrict__ b0, const float* __restrict__ b1,
           const float* __restrict__ b2, const float* __restrict__ b3,
           const float* __restrict__ gamma, const float* __restrict__ beta,
           float* __restrict__ out)
{
  extern __shared__ char st[];
  const int tid  = threadIdx.x;
  const int wl   = tid >> 5;            // warp 0..7
  const int lane = tid & 31;
  const int gg   = blockIdx.x;          // graph id

  float* sG  = (float*)(st + O_G);
  float* sBe = (float*)(st + O_BE);
  float* sS  = (float*)(st + O_SS);
  float* sSw = (float*)(st + O_SW);
  float* xnat  = (float*)st;            // init fp32 scratch (aliases XT+Y span, 42240<=45056)
  float* xnat2 = (float*)st;            // final fp32 out (same alias; tiles dead at L==3 epi)

  const u32 sb   = (u32)__cvta_generic_to_shared(st);
  const u32 xt_b = sb + XT_OF;
  const u32 y_b  = sb + Y_OF;

  const int rsel = lane & 15;
  const int csel = (lane >> 4) << 3;
  const int r0   = lane >> 2;
  const int cc   = (lane & 3) * 2;

  // trans-ldmatrix lane addressing (stage1 B from xT[d][n])
  const int t4row = ((lane >> 4) << 3) + (lane & 7);   // d offset within 16-k step
  const int t4col = ((lane >> 3) & 1) * 8;             // n-block offset within pair
  const int t2row = ((lane >> 3) & 1) * 8 + (lane & 7);

  // warp-tile coordinates (fixed ownership across layers, both GEMMs + residual)
  const int mr = (wl >> 1) * 32;   // o stripe
  const int nb = (wl & 1) * 40;    // m half (stage1) / n half (stage2)

  const float* Bs[4] = {b0, b1, b2, b3};

  // ================= init =================
  {
    const float4* src = (const float4*)(lm + (size_t)gg * (LMN*128));
    for (int i = tid; i < LMN*32; i += NT){
      int row = i >> 5, c4 = i & 31;
      ((float4*)(xnat + row*132))[c4] = src[i];
    }
  }
  if (tid < 128){ sG[tid] = gamma[tid]; sBe[tid] = beta[tid]; }
  __syncthreads();

  // region-pool scores
  {
    const float brv = __ldg(br);
    const float4 wv = __ldg((const float4*)Wr + lane);
    for (int n = wl; n < LMN; n += 8){
      float4 xv = ((const float4*)(xnat + n*132))[lane];
      float d = xv.x*wv.x + xv.y*wv.y + xv.z*wv.z + xv.w*wv.w;
      #pragma unroll
      for (int o = 16; o; o >>= 1) d += __shfl_xor_sync(0xffffffffu, d, o);
      if (lane == 0) sS[n] = d + brv;
    }
  }
  __syncthreads();
  if (tid < 9){
    int2 re = c_reg[tid];
    float mx = -3.4e38f;
    for (int n = re.x; n <= re.y; n++) mx = fmaxf(mx, sS[n]);
    float sum = 0.f;
    for (int n = re.x; n <= re.y; n++){ float e = expf(sS[n]-mx); sSw[n] = e; sum += e; }
    float inv = 1.f/sum;
    for (int n = re.x; n <= re.y; n++) sSw[n] *= inv;
  }
  __syncthreads();
  for (int i = tid; i < 9*128; i += NT){
    int r = i >> 7, d = i & 127;
    int2 re = c_reg[r];
    float acc = 0.f;
    for (int n = re.x; n <= re.y; n++) acc = fmaf(sSw[n], xnat[n*132 + d], acc);
    xnat[(LMN + r)*132 + d] = acc;
  }
  __syncthreads();

  // ---- residual init (register-resident, stage2 C-frag shaped, fp32 exact) ----
  float resid[40];
  #pragma unroll
  for (int sb2 = 0; sb2 < 2; sb2++)
    #pragma unroll
    for (int j = 0; j < 5; j++)
      #pragma unroll
      for (int h = 0; h < 2; h++)
        #pragma unroll
        for (int e = 0; e < 2; e++){
          int row = mr + sb2*16 + r0 + h*8;       // o / d
          int col = nb + j*8 + cc + e;            // n
          resid[(sb2*5+j)*4 + h*2 + e] = (col < NTOT) ? xnat[col*132 + row] : 0.f;
        }

  // ---- build initial xT[d 128][n 80] fp16 (stage-to-regs, then overwrite alias) ----
  {
    const int d  = tid >> 1;
    const int n0 = (tid & 1) * 40;
    float v[40];
    #pragma unroll
    for (int j = 0; j < 40; j++){
      int n = n0 + j;
      v[j] = (n < NTOT) ? xnat[n*132 + d] : 0.f;
    }
    __syncthreads();   // all xnat reads done before writing over the alias
    #pragma unroll
    for (int c = 0; c < 5; c++){
      u32 H[4];
      #pragma unroll
      for (int p = 0; p < 4; p++)
        H[p] = h2pack(v[c*8 + p*2], v[c*8 + p*2 + 1]);
      *(uint4*)(st + XT_OF + (u32)(d*XSTRB + (n0 + c*8)*2)) = make_uint4(H[0],H[1],H[2],H[3]);
    }
  }
  __syncthreads();

  // ================= layer loop =================
  #pragma unroll 1
  for (int L = 0; L < 4; L++){
    // ---------- stage1: Y[o][m] = W^T @ x^T ; warp tile 32o x 40m, K=128 ----------
    // A = W^T fp16 A-frags (global, L1-hot), B = xT tile via ldmatrix.trans
    {
      const int band0 = (wl >> 1) * 2;
      float acc[40];
      #pragma unroll
      for (int q = 0; q < 40; q++) acc[q] = 0.f;
      #pragma unroll
      for (int k = 0; k < 8; k++){
        u32 f01[4], f23[4], f4[2];
        {
          u32 rbase = xt_b + (u32)((k*16 + t4row)*XSTRB);
          ldm4t(f01, rbase + (u32)((nb      + t4col)*2));
          ldm4t(f23, rbase + (u32)((nb + 16 + t4col)*2));
          ldm2t(f4, xt_b + (u32)((k*16 + t2row)*XSTRB + (nb + 32)*2));
        }
        u32 B0[5] = {f01[0], f01[1], f23[0], f23[1], f4[0]};
        u32 B1[5] = {f01[2], f01[3], f23[2], f23[3], f4[1]};
        #pragma unroll
        for (int sb2 = 0; sb2 < 2; sb2++){
          uint4 aH = g_wf[((L*8 + band0 + sb2)*8 + k)*32 + lane];
          #pragma unroll
          for (int j = 0; j < 5; j++)
            mma(acc + (sb2*5 + j)*4, (const u32*)&aH, B0[j], B1[j]);
        }
      }
      // store Y (fp16, m-adjacent pairs pack into u32)
      #pragma unroll
      for (int sb2 = 0; sb2 < 2; sb2++)
        #pragma unroll
        for (int j = 0; j < 5; j++)
          #pragma unroll
          for (int h = 0; h < 2; h++){
            const float* c = acc + (sb2*5 + j)*4;
            int o = mr + sb2*16 + r0 + h*8;
            int m = nb + j*8 + cc;
            *(u32*)(st + Y_OF + (u32)(o*YSTR + m*2)) = h2pack(c[h*2], c[h*2+1]);
          }
    }
    __syncthreads();

    // ---------- stage2: outT[o][n] = Y @ adj^T ; warp tile 32o x 40n, K=80 ----------
    // A = Y (smem, ldmatrix row-major), B = adj^T fp16 B-frags (global, 256B/frag)
    {
      float acc[40];
      #pragma unroll
      for (int q = 0; q < 40; q++) acc[q] = 0.f;
      const int jb = nb >> 3;   // first n-block index
      #pragma unroll
      for (int k = 0; k < 5; k++){
        const int kc = k*16 + csel;
        u32 a0[4], a1[4];
        ldm4(a0, y_b + (u32)((mr      + rsel)*YSTR + kc*2));
        ldm4(a1, y_b + (u32)((mr + 16 + rsel)*YSTR + kc*2));
        #pragma unroll
        for (int j = 0; j < 5; j++){
          uint2 bf = g_bf[(k*10 + jb + j)*32 + lane];
          mma(acc + j*4,        a0, bf.x, bf.y);
          mma(acc + (5 + j)*4,  a1, bf.x, bf.y);
        }
      }
      // epilogue: bias + relu (+ residual from regs), packed u32 stores into xT
      if (L == 3) __syncthreads();   // all Y/xT tile reads settled before alias overwrite
      #pragma unroll
      for (int sb2 = 0; sb2 < 2; sb2++){
        const float bias0 = __ldg(Bs[L] + mr + sb2*16 + r0);
        const float bias1 = __ldg(Bs[L] + mr + sb2*16 + r0 + 8);
        #pragma unroll
        for (int j = 0; j < 5; j++){
          float* c = acc + (sb2*5 + j)*4;
          #pragma unroll
          for (int h = 0; h < 2; h++){
            const float bia = h ? bias1 : bias0;
            const int idx = (sb2*5+j)*4 + h*2;
            const int row = mr + sb2*16 + r0 + h*8;  // o / d
            const int col = nb + j*8 + cc;           // n
            if (L < 3){
              float f0 = fmaxf(c[h*2]     + bia, 0.f) + resid[idx];
              float f1 = fmaxf(c[h*2 + 1] + bia, 0.f) + resid[idx+1];
              resid[idx]   = f0;
              resid[idx+1] = f1;
              *(u32*)(st + XT_OF + (u32)(row*XSTRB + col*2)) = h2pack(f0,f1);
            } else {
              float f0 = fmaxf(c[h*2]     + bia, 0.f);
              float f1 = fmaxf(c[h*2 + 1] + bia, 0.f);
              if (col   < NTOT) xnat2[col*132 + row]     = f0;
              if (col+1 < NTOT) xnat2[(col+1)*132 + row] = f1;
            }
          }
        }
      }
    }
    __syncthreads();
  }

  // ================= LayerNorm + writeout =================
  {
    const float4 gv  = ((const float4*)sG)[lane];
    const float4 bev = ((const float4*)sBe)[lane];
    for (int n = wl; n < NTOT; n += 8){
      float4 v = *(const float4*)(xnat2 + n*132 + lane*4);
      float s  = v.x + v.y + v.z + v.w;
      float s2 = v.x*v.x + v.y*v.y + v.z*v.z + v.w*v.w;
      #pragma unroll
      for (int o = 16; o; o >>= 1){
        s  += __shfl_xor_sync(0xffffffffu, s,  o);
        s2 += __shfl_xor_sync(0xffffffffu, s2, o);
      }
      float mu  = s * (1.f/128.f);
      float var = s2 * (1.f/128.f) - mu*mu;
      float inv = rsqrtf(var + 1e-5f);
      float4 o4;
      o4.x = (v.x - mu)*inv*gv.x + bev.x;
      o4.y = (v.y - mu)*inv*gv.y + bev.y;
      o4.z = (v.z - mu)*inv*gv.z + bev.z;
      o4.w = (v.w - mu)*inv*gv.w + bev.w;
      ((float4*)(out + ((size_t)gg*NTOT + n)*128))[lane] = o4;
    }
  }
}

extern "C" void kernel_launch(void* const* d_in, const int* in_sizes, int n_in,
                              void* d_out, int out_size)
{
  const float* lm    = (const float*)d_in[0];
  const float* adj   = (const float*)d_in[1];
  const float* Wr    = (const float*)d_in[2];
  const float* br    = (const float*)d_in[3];
  const float* W0    = (const float*)d_in[4];
  const float* b0    = (const float*)d_in[5];
  const float* W1    = (const float*)d_in[6];
  const float* b1    = (const float*)d_in[7];
  const float* W2    = (const float*)d_in[8];
  const float* b2    = (const float*)d_in[9];
  const float* W3    = (const float*)d_in[10];
  const float* b3    = (const float*)d_in[11];
  const float* gamma = (const float*)d_in[12];
  const float* beta  = (const float*)d_in[13];
  float* out = (float*)d_out;

  format_kernel<<<5, 256>>>(adj, W0, W1, W2, W3);
  cudaFuncSetAttribute(net_kernel, cudaFuncAttributeMaxDynamicSharedMemorySize, SMEM_SZ);
  net_kernel<<<4096, NT, SMEM_SZ>>>(lm, Wr, br, b0, b1, b2, b3, gamma, beta, out);
}